// round 3
// baseline (speedup 1.0000x reference)
#include <cuda_runtime.h>
#include <cuda_bf16.h>
#include <cstdint>

// out[t, d] = code[weight[row, d]] * absmax[row],  row = tokens[t]
// tokens [8192], weight [50400,4096] int32 codes, absmax [50400], code [256].
// Output [8192,4096] fp32. HBM-bound: 134 MB read + 134 MB write.
//
// R2 -> R3: bank-replicated LUT (32 copies, s[idx*32+lane]) makes every
// shared lookup conflict-free regardless of the random code indices.
// Default cache policy restored (.cs hints regressed: L2 write-back was
// absorbing a large fraction of the output traffic).

static constexpr int DIM = 4096;
static constexpr int THREADS = 256;
static constexpr int VEC_PER_THREAD = DIM / 4 / THREADS;  // 4 int4 per thread

__global__ __launch_bounds__(THREADS)
void bnb_embed_kernel(const int* __restrict__ tokens,
                      const int* __restrict__ weight,
                      const float* __restrict__ absmax,
                      const float* __restrict__ code,
                      float* __restrict__ out,
                      int n_tokens)
{
    // 32 bank-replicated copies of the 256-entry LUT: entry i for lane l
    // lives at s_code[i*32 + l] -> bank == l, conflict-free always.
    __shared__ float s_code[256 * 32];
    const int tid  = threadIdx.x;
    const int lane = tid & 31;
    const int wid  = tid >> 5;             // 8 warps

    // Fill: warp w handles entries {w, w+8, w+16, ...}; each warp-store hits
    // 32 distinct banks (lane varies, idx fixed) -> conflict-free.
    for (int i = wid; i < 256; i += 8) {
        s_code[i * 32 + lane] = code[i];   // broadcast load, cached
    }
    __syncthreads();

    const float* __restrict__ my_lut = s_code + lane;

    for (int t = blockIdx.x; t < n_tokens; t += gridDim.x) {
        const int row = __ldg(&tokens[t]);
        const float scale = __ldg(&absmax[row]);

        const int4* __restrict__ wrow =
            reinterpret_cast<const int4*>(weight + (long long)row * DIM);
        float4* __restrict__ orow =
            reinterpret_cast<float4*>(out + (long long)t * DIM);

        // Front-batch: 4 outstanding 16B loads per thread.
        int4 q[VEC_PER_THREAD];
#pragma unroll
        for (int i = 0; i < VEC_PER_THREAD; i++)
            q[i] = wrow[tid + i * THREADS];

#pragma unroll
        for (int i = 0; i < VEC_PER_THREAD; i++) {
            float4 v;
            v.x = my_lut[q[i].x << 5] * scale;
            v.y = my_lut[q[i].y << 5] * scale;
            v.z = my_lut[q[i].z << 5] * scale;
            v.w = my_lut[q[i].w << 5] * scale;
            orow[tid + i * THREADS] = v;
        }
    }
}

extern "C" void kernel_launch(void* const* d_in, const int* in_sizes, int n_in,
                              void* d_out, int out_size)
{
    const int*   tokens = (const int*)d_in[0];
    const int*   weight = (const int*)d_in[1];
    const float* absmax = (const float*)d_in[2];
    const float* code   = (const float*)d_in[3];
    float*       out    = (float*)d_out;

    const int n_tokens = in_sizes[0];   // 8192
    // 32 KB smem/CTA -> 7 CTAs/SM on 228 KB; persistent grid 7 x 148.
    const int grid = 7 * 148;
    bnb_embed_kernel<<<grid, THREADS>>>(tokens, weight, absmax, code, out, n_tokens);
}

// round 4
// speedup vs baseline: 1.2746x; 1.2746x over previous
#include <cuda_runtime.h>
#include <cuda_bf16.h>
#include <cstdint>

// out[t, d] = code[weight[row, d]] * absmax[row],  row = tokens[t]
// tokens [8192], weight [50400,4096] int32 codes, absmax [50400], code [256].
// Output [8192,4096] fp32. HBM-bound: 134 MB read + 134 MB write.
//
// R3 -> R4: revert bank-replicated LUT (conflicts weren't binding; occupancy
// loss was the real cost). Back to R1 structure, but 512-thread CTAs cover
// TWO tokens each: same 4 int4 registers per thread, now split across two
// independent load->LUT->store chains, doubling the latency-hiding window.

static constexpr int DIM = 4096;
static constexpr int THREADS = 512;
static constexpr int VECS = DIM / 4;                 // 1024 int4 per row
static constexpr int VPT = VECS / THREADS;           // 2 int4 per thread per token

__global__ __launch_bounds__(THREADS)
void bnb_embed_kernel(const int* __restrict__ tokens,
                      const int* __restrict__ weight,
                      const float* __restrict__ absmax,
                      const float* __restrict__ code,
                      float* __restrict__ out,
                      int n_tokens)
{
    __shared__ float s_code[256];
    const int tid = threadIdx.x;
    if (tid < 256) s_code[tid] = code[tid];
    __syncthreads();

    const int tA = blockIdx.x * 2;
    const int tB = tA + 1;
    const bool hasB = (tB < n_tokens);

    const int rowA = __ldg(&tokens[tA]);
    const int rowB = hasB ? __ldg(&tokens[tB]) : rowA;
    const float scaleA = __ldg(&absmax[rowA]);
    const float scaleB = __ldg(&absmax[rowB]);

    const int4* __restrict__ wA =
        reinterpret_cast<const int4*>(weight + (long long)rowA * DIM);
    const int4* __restrict__ wB =
        reinterpret_cast<const int4*>(weight + (long long)rowB * DIM);
    float4* __restrict__ oA = reinterpret_cast<float4*>(out + (long long)tA * DIM);
    float4* __restrict__ oB = reinterpret_cast<float4*>(out + (long long)tB * DIM);

    // Front-batch all 4 loads: two independent rows in flight.
    int4 qA[VPT], qB[VPT];
#pragma unroll
    for (int i = 0; i < VPT; i++) qA[i] = wA[tid + i * THREADS];
#pragma unroll
    for (int i = 0; i < VPT; i++) qB[i] = wB[tid + i * THREADS];

    // Process token A while B's loads are still streaming in.
#pragma unroll
    for (int i = 0; i < VPT; i++) {
        float4 v;
        v.x = s_code[qA[i].x] * scaleA;
        v.y = s_code[qA[i].y] * scaleA;
        v.z = s_code[qA[i].z] * scaleA;
        v.w = s_code[qA[i].w] * scaleA;
        oA[tid + i * THREADS] = v;
    }
    if (hasB) {
#pragma unroll
        for (int i = 0; i < VPT; i++) {
            float4 v;
            v.x = s_code[qB[i].x] * scaleB;
            v.y = s_code[qB[i].y] * scaleB;
            v.z = s_code[qB[i].z] * scaleB;
            v.w = s_code[qB[i].w] * scaleB;
            oB[tid + i * THREADS] = v;
        }
    }
}

extern "C" void kernel_launch(void* const* d_in, const int* in_sizes, int n_in,
                              void* d_out, int out_size)
{
    const int*   tokens = (const int*)d_in[0];
    const int*   weight = (const int*)d_in[1];
    const float* absmax = (const float*)d_in[2];
    const float* code   = (const float*)d_in[3];
    float*       out    = (float*)d_out;

    const int n_tokens = in_sizes[0];        // 8192
    const int grid = (n_tokens + 1) / 2;     // 4096 CTAs, 2 tokens each
    bnb_embed_kernel<<<grid, THREADS>>>(tokens, weight, absmax, code, out, n_tokens);
}